// round 5
// baseline (speedup 1.0000x reference)
#include <cuda_runtime.h>
#include <cstdint>

#define DIM   768
#define POOL  20
#define NPAIR 10
#define TOPK  9
#define NVEC  6                 // float4 chunks per lane: 768/4/32
#define ROWS_PER_BLOCK 16       // 8 warps x 2 rows

// Allocation-free scratch
__device__ unsigned long long g_kp[NPAIR * DIM];  // packed key pairs, 60 KB
__device__ float              g_rowsum[POOL];
__device__ unsigned int       g_count[POOL];
__device__ unsigned int       g_done = 0;

// ---------------- f32x2 packed-math helpers (FFMA2 path) -------------------
__device__ __forceinline__ unsigned long long f2pk(float lo, float hi) {
    unsigned long long r;
    asm("mov.b64 %0, {%1,%2};" : "=l"(r) : "f"(lo), "f"(hi));
    return r;
}
__device__ __forceinline__ void ffma2(unsigned long long& d,
                                      unsigned long long a,
                                      unsigned long long b) {
    asm("fma.rn.f32x2 %0, %1, %2, %0;" : "+l"(d) : "l"(a), "l"(b));
}
__device__ __forceinline__ unsigned long long fadd2(unsigned long long a,
                                                    unsigned long long b) {
    unsigned long long r;
    asm("add.rn.f32x2 %0, %1, %2;" : "=l"(r) : "l"(a), "l"(b));
    return r;
}
__device__ __forceinline__ float2 pk_unpack(unsigned long long v) {
    float2 r;
    asm("mov.b64 {%0,%1}, %2;" : "=f"(r.x), "=f"(r.y) : "l"(v));
    return r;
}

// ---------------------------------------------------------------------------
// prep: 1 block x 640 threads. Warp w computes inv-norm of key w; then all
// threads fill the packed pair table g_kp[p*DIM + d] = (k2p[d]*i2p, k2p+1[d]*i2p+1).
// ---------------------------------------------------------------------------
__global__ void prep_kernel(const float* __restrict__ keys,
                            const int*   __restrict__ layer)
{
    __shared__ float s_inv[POOL];
    const int w    = threadIdx.x >> 5;
    const int lane = threadIdx.x & 31;
    const float* __restrict__ kbase = keys + (size_t)(*layer) * POOL * DIM;

    if (w < POOL) {
        const float* __restrict__ krow = kbase + (size_t)w * DIM;
        float ss = 0.f;
        #pragma unroll
        for (int i = 0; i < DIM / 32; i++) {
            float v = __ldg(krow + lane + 32 * i);
            ss += v * v;
        }
        #pragma unroll
        for (int off = 16; off; off >>= 1)
            ss += __shfl_xor_sync(0xffffffffu, ss, off);
        if (lane == 0)
            s_inv[w] = 1.f / fmaxf(sqrtf(ss), 1e-12f);
    }
    if (threadIdx.x < POOL) {
        g_count[threadIdx.x]  = 0u;
        g_rowsum[threadIdx.x] = 0.f;
    }
    __syncthreads();

    for (int u = threadIdx.x; u < NPAIR * DIM; u += blockDim.x) {
        const int p = u / DIM;
        const int d = u - p * DIM;
        const float lo = __ldg(kbase + (size_t)(2 * p)     * DIM + d) * s_inv[2 * p];
        const float hi = __ldg(kbase + (size_t)(2 * p + 1) * DIM + d) * s_inv[2 * p + 1];
        g_kp[u] = f2pk(lo, hi);
    }
}

// ---------------------------------------------------------------------------
// top-9 on a 20-vector in registers (predicated, no dynamic indexing)
// ---------------------------------------------------------------------------
__device__ __forceinline__ uint64_t topk_pack(float* s)
{
    uint64_t packed = 0;
    #pragma unroll
    for (int t = 0; t < TOPK; t++) {
        float best = -3.4e38f; int bj = 0;
        #pragma unroll
        for (int j = 0; j < POOL; j++)
            if (s[j] > best) { best = s[j]; bj = j; }
        packed |= (uint64_t)bj << (7 * t);
        #pragma unroll
        for (int j = 0; j < POOL; j++)
            if (j == bj) s[j] = -3.4e38f;
    }
    return packed;
}

// ---------------------------------------------------------------------------
// main (fused): sims via FFMA2 -> SEL top-k -> gather+store; last block
// computes dist and writes the output tail.
// ---------------------------------------------------------------------------
__global__ void __launch_bounds__(256)
pool_main(const float* __restrict__ x,
          const float* __restrict__ prompts,
          const int*   __restrict__ layer,
          float*       __restrict__ out,
          int B, long long total, long long out_sz)
{
    __shared__ unsigned int s_count[POOL];
    __shared__ unsigned int s_last;
    if (threadIdx.x < POOL) s_count[threadIdx.x] = 0u;
    __syncthreads();

    const int warp = threadIdx.x >> 5;
    const int lane = threadIdx.x & 31;
    const int r0   = blockIdx.x * ROWS_PER_BLOCK + warp * 2;
    const int r1c  = r0 + 1;
    const bool has1 = (r1c < B);
    const int r1   = has1 ? r1c : r0;

    if (r0 < B) {
        const float4* __restrict__ xr0 = (const float4*)(x + (size_t)r0 * DIM);
        const float4* __restrict__ xr1 = (const float4*)(x + (size_t)r1 * DIM);
        const ulonglong2* __restrict__ kp = (const ulonglong2*)g_kp;

        unsigned long long a0[NPAIR], a1[NPAIR], ssp0 = 0ull, ssp1 = 0ull;
        #pragma unroll
        for (int p = 0; p < NPAIR; p++) { a0[p] = 0ull; a1[p] = 0ull; }

        #pragma unroll
        for (int i = 0; i < NVEC; i++) {
            const float4 xv0 = __ldcs(xr0 + lane + 32 * i);
            const float4 xv1 = __ldcs(xr1 + lane + 32 * i);
            unsigned long long x0p[4] = { f2pk(xv0.x, xv0.x), f2pk(xv0.y, xv0.y),
                                          f2pk(xv0.z, xv0.z), f2pk(xv0.w, xv0.w) };
            unsigned long long x1p[4] = { f2pk(xv1.x, xv1.x), f2pk(xv1.y, xv1.y),
                                          f2pk(xv1.z, xv1.z), f2pk(xv1.w, xv1.w) };
            #pragma unroll
            for (int c = 0; c < 4; c++) { ffma2(ssp0, x0p[c], x0p[c]);
                                          ffma2(ssp1, x1p[c], x1p[c]); }
            const int e = 2 * (lane + 32 * i);   // ulonglong2 index: dims 4*(lane+32i)..+3
            #pragma unroll
            for (int p = 0; p < NPAIR; p++) {
                const ulonglong2 kv0 = __ldg(kp + p * (DIM / 2) + e);
                const ulonglong2 kv1 = __ldg(kp + p * (DIM / 2) + e + 1);
                ffma2(a0[p], x0p[0], kv0.x); ffma2(a0[p], x0p[1], kv0.y);
                ffma2(a0[p], x0p[2], kv1.x); ffma2(a0[p], x0p[3], kv1.y);
                ffma2(a1[p], x1p[0], kv0.x); ffma2(a1[p], x1p[1], kv0.y);
                ffma2(a1[p], x1p[2], kv1.x); ffma2(a1[p], x1p[3], kv1.y);
            }
        }

        // butterfly reduce 22 packed accumulators
        #pragma unroll
        for (int off = 16; off; off >>= 1) {
            ssp0 = fadd2(ssp0, __shfl_xor_sync(0xffffffffu, ssp0, off));
            ssp1 = fadd2(ssp1, __shfl_xor_sync(0xffffffffu, ssp1, off));
            #pragma unroll
            for (int p = 0; p < NPAIR; p++) {
                a0[p] = fadd2(a0[p], __shfl_xor_sync(0xffffffffu, a0[p], off));
                a1[p] = fadd2(a1[p], __shfl_xor_sync(0xffffffffu, a1[p], off));
            }
        }

        const float inv0 = 1.f / fmaxf(sqrtf(pk_unpack(ssp0).x), 1e-12f);
        const float inv1 = 1.f / fmaxf(sqrtf(pk_unpack(ssp1).x), 1e-12f);

        // SEL: lanes 0-15 process row0, lanes 16-31 row1 (one top-k for 2 rows)
        const bool hi_half = (lane >= 16);
        const float inv = hi_half ? inv1 : inv0;
        float s[POOL];
        #pragma unroll
        for (int p = 0; p < NPAIR; p++) {
            const float2 v0 = pk_unpack(a0[p]);
            const float2 v1 = pk_unpack(a1[p]);
            s[2 * p]     = (hi_half ? v1.x : v0.x) * inv;
            s[2 * p + 1] = (hi_half ? v1.y : v0.y) * inv;
        }

        // dist bookkeeping: pool-sum of sim rows 0..19
        float rs = 0.f;
        #pragma unroll
        for (int j = 0; j < POOL; j++) rs += s[j];
        if (lane == 0  && r0 < POOL) g_rowsum[r0] = rs;
        if (lane == 16 && has1 && r1 < POOL) g_rowsum[r1] = rs;

        const uint64_t pk_res = topk_pack(s);
        const uint64_t p0 = __shfl_sync(0xffffffffu, pk_res, 0);
        const uint64_t p1 = __shfl_sync(0xffffffffu, pk_res, 16);

        if (lane == 0) {
            #pragma unroll
            for (int t = 0; t < TOPK; t++)
                atomicAdd(&s_count[(int)((p0 >> (7 * t)) & 127)], 1u);
        }
        if (lane == 16 && has1) {
            #pragma unroll
            for (int t = 0; t < TOPK; t++)
                atomicAdd(&s_count[(int)((p1 >> (7 * t)) & 127)], 1u);
        }

        // gather: copy selected prompt rows, coalesced streaming stores
        const float4* __restrict__ pbase =
            (const float4*)(prompts + (size_t)(*layer) * POOL * DIM);
        float4* __restrict__ o0 = (float4*)out + (size_t)r0 * (TOPK * DIM / 4);
        float4* __restrict__ o1 = (float4*)out + (size_t)r1c * (TOPK * DIM / 4);
        #pragma unroll
        for (int t = 0; t < TOPK; t++) {
            const float4* pr0 = pbase + (int)((p0 >> (7 * t)) & 127) * (DIM / 4);
            #pragma unroll
            for (int i = 0; i < NVEC; i++)
                __stcs(o0 + t * (DIM / 4) + lane + 32 * i, __ldg(pr0 + lane + 32 * i));
        }
        if (has1) {
            #pragma unroll
            for (int t = 0; t < TOPK; t++) {
                const float4* pr1 = pbase + (int)((p1 >> (7 * t)) & 127) * (DIM / 4);
                #pragma unroll
                for (int i = 0; i < NVEC; i++)
                    __stcs(o1 + t * (DIM / 4) + lane + 32 * i, __ldg(pr1 + lane + 32 * i));
            }
        }
    }

    __syncthreads();
    if (threadIdx.x < POOL)
        atomicAdd(&g_count[threadIdx.x], s_count[threadIdx.x]);

    // last-block finalize: dist = 1 - sum_r count[r]*rowsum[r] / (B*9*20)
    __threadfence();
    if (threadIdx.x == 0)
        s_last = (atomicAdd(&g_done, 1u) == gridDim.x - 1) ? 1u : 0u;
    __syncthreads();
    if (s_last && threadIdx.x == 0) {
        double acc = 0.0;
        #pragma unroll
        for (int r = 0; r < POOL; r++)
            acc += (double)g_count[r] * (double)g_rowsum[r];
        const float dist = (float)(1.0 - acc / ((double)B * TOPK * POOL));
        for (long long i = total; i < out_sz; i++) out[i] = dist;
        g_done = 0;   // reset for next graph replay
    }
}

extern "C" void kernel_launch(void* const* d_in, const int* in_sizes, int n_in,
                              void* d_out, int out_size)
{
    const float* x       = (const float*)d_in[0];
    const float* keys    = (const float*)d_in[1];
    const float* prompts = (const float*)d_in[2];
    const int*   layer   = (const int*)d_in[3];

    const int B = in_sizes[0] / DIM;
    const long long total = (long long)B * TOPK * DIM;

    prep_kernel<<<1, 640>>>(keys, layer);
    pool_main<<<(B + ROWS_PER_BLOCK - 1) / ROWS_PER_BLOCK, 256>>>(
        x, prompts, layer, (float*)d_out, B, total, (long long)out_size);
}